// round 2
// baseline (speedup 1.0000x reference)
#include <cuda_runtime.h>
#include <cstdint>
#include <math.h>

// ---------------- problem constants ----------------
constexpr int Bc  = 8;
constexpr int Tc  = 256;
constexpr int Cc  = 1024;
constexpr int QDc = 768;
constexpr int LQc = 24;
constexpr int Wc  = 16;
constexpr int Kc  = 4;
constexpr int CCc = 4;       // W/K
constexpr int NWc = 241;     // T - W + 1
constexpr int Sc  = 8;
constexpr int Hc  = 4;
constexpr int HDc = 256;     // C/H
constexpr int SLc = 964;     // NW*K

constexpr int PRED_SZ = Bc * 2 * NWc;  // 3856

// ---------------- scratch (device globals; no allocation allowed) ----------------
__device__ float g_xpe   [Bc * Tc * Cc];
__device__ float g_qpe   [Bc * LQc * QDc];
__device__ float g_v     [Bc * Tc * Cc];
__device__ float g_vw2   [Bc * Tc * Cc];
__device__ float g_e1    [Bc * LQc * Cc];
__device__ float g_e2    [Bc * LQc * Cc];
__device__ float g_e2k   [Bc * LQc * Cc];
__device__ int   g_labels[Bc * Tc];
__device__ int   g_mode  [Bc * SLc];
__device__ float g_qq    [Bc * SLc * Cc];
__device__ float g_qbuf  [Bc * SLc * Cc];
__device__ float g_vbuf  [Bc * SLc * Cc];
__device__ float g_khmat [Bc * SLc * Cc];
__device__ float g_scores[(long)Bc * Hc * SLc * SLc];
__device__ float g_attn  [Bc * SLc * Cc];
__device__ float g_outb  [Bc * SLc * Cc];
__device__ float g_hbuf  [Bc * NWc * Cc];
__device__ float g_mp    [Bc * Sc * Cc];

// ---------------- generic tiled GEMM ----------------
// C[m,n] = alpha * sum_k A[m,k] * B(k,n)  (+ bias[n]) (+relu)
// TRANSB=true : B row-major (N,K)  -> B[n*ldb + k]   ("x @ W^T")
// TRANSB=false: B row-major (K,N)  -> B[k*ldb + n]
// batching: z = blockIdx.z ; z1 = z/bdiv ; z2 = z%bdiv; offsets = z1*s?1 + z2*s?2
template<bool TRANSB, bool RELU>
__global__ void gemm_kernel(const float* __restrict__ A, int lda, long sA1, long sA2,
                            const float* __restrict__ B, int ldb, long sB1, long sB2,
                            float* __restrict__ Cm, int ldc, long sC1, long sC2,
                            int M, int N, int K, int bdiv,
                            const float* __restrict__ bias, float alpha)
{
    const int z = blockIdx.z, z1 = z / bdiv, z2 = z % bdiv;
    A  += z1 * sA1 + z2 * sA2;
    B  += z1 * sB1 + z2 * sB2;
    Cm += z1 * sC1 + z2 * sC2;

    __shared__ float As[16][64];
    __shared__ float Bs[16][64];

    const int tid = threadIdx.x;        // 256 threads
    const int tx = tid & 15, ty = tid >> 4;
    const int rowBase = blockIdx.y * 64;
    const int colBase = blockIdx.x * 64;

    float acc[4][4] = {};

    for (int k0 = 0; k0 < K; k0 += 16) {
#pragma unroll
        for (int i = 0; i < 4; i++) {
            int l = tid + i * 256;
            int m = l >> 4, kk = l & 15;
            int gm = rowBase + m, gk = k0 + kk;
            As[kk][m] = (gm < M && gk < K) ? A[(long)gm * lda + gk] : 0.f;
        }
#pragma unroll
        for (int i = 0; i < 4; i++) {
            int l = tid + i * 256;
            if (TRANSB) {
                int n = l >> 4, kk = l & 15;
                int gn = colBase + n, gk = k0 + kk;
                Bs[kk][n] = (gn < N && gk < K) ? B[(long)gn * ldb + gk] : 0.f;
            } else {
                int kk = l >> 6, n = l & 63;
                int gn = colBase + n, gk = k0 + kk;
                Bs[kk][n] = (gn < N && gk < K) ? B[(long)gk * ldb + gn] : 0.f;
            }
        }
        __syncthreads();
#pragma unroll
        for (int kk = 0; kk < 16; kk++) {
            float ra[4], rb[4];
#pragma unroll
            for (int i = 0; i < 4; i++) ra[i] = As[kk][ty * 4 + i];
#pragma unroll
            for (int j = 0; j < 4; j++) rb[j] = Bs[kk][tx * 4 + j];
#pragma unroll
            for (int i = 0; i < 4; i++)
#pragma unroll
                for (int j = 0; j < 4; j++)
                    acc[i][j] += ra[i] * rb[j];
        }
        __syncthreads();
    }

#pragma unroll
    for (int i = 0; i < 4; i++) {
        int gm = rowBase + ty * 4 + i;
        if (gm >= M) continue;
#pragma unroll
        for (int j = 0; j < 4; j++) {
            int gn = colBase + tx * 4 + j;
            if (gn >= N) continue;
            float val = acc[i][j] * alpha + (bias ? bias[gn] : 0.f);
            if (RELU) val = fmaxf(val, 0.f);
            Cm[(long)gm * ldc + gn] = val;
        }
    }
}

// ---------------- positional encoding add ----------------
__global__ void add_pe_kernel(const float* __restrict__ src, float* __restrict__ dst,
                              int n, int L, int D)
{
    int idx = blockIdx.x * blockDim.x + threadIdx.x;
    if (idx >= n) return;
    int c = idx % D;
    int pos = (idx / D) % L;
    int i2 = (c >> 1) * 2;
    float freq = expf((float)i2 * (-logf(10000.f) / (float)D));
    float ang = (float)pos * freq;
    float pe = (c & 1) ? cosf(ang) : sinf(ang);
    dst[idx] = src[idx] + pe;
}

// ---------------- sim + argmax(labels) fused ----------------
__global__ void sim_argmax_kernel(const float* __restrict__ v, const float* __restrict__ e1,
                                  int* __restrict__ labels)
{
    const int bt = blockIdx.x;          // b*T + t
    const int b = bt / Tc;
    __shared__ float sv[Cc];
    __shared__ float red[4];
    const int tid = threadIdx.x;        // 128 threads
    const int lane = tid & 31, warp = tid >> 5;

    const float* vrow = v + (long)bt * Cc;
    for (int i = tid; i < Cc; i += 128) sv[i] = vrow[i];
    __syncthreads();

    __shared__ float best;
    __shared__ int bestl;
    if (tid == 0) { best = -INFINITY; bestl = 0; }
    __syncthreads();

    for (int l = 0; l < LQc; l++) {
        const float* er = e1 + ((long)b * LQc + l) * Cc;
        float s = 0.f;
        for (int i = tid; i < Cc; i += 128) s += sv[i] * er[i];
#pragma unroll
        for (int o = 16; o; o >>= 1) s += __shfl_down_sync(0xffffffff, s, o);
        if (lane == 0) red[warp] = s;
        __syncthreads();
        if (tid == 0) {
            float tot = red[0] + red[1] + red[2] + red[3];
            if (tot > best) { best = tot; bestl = l; }
        }
        __syncthreads();
    }
    if (tid == 0) labels[bt] = bestl;
}

// ---------------- window mean pooling (+ b_v2) ----------------
__global__ void pool_kernel(const float* __restrict__ vw2, const float* __restrict__ b_v2,
                            float* __restrict__ qq)
{
    long idx = (long)blockIdx.x * blockDim.x + threadIdx.x;
    if (idx >= (long)Bc * SLc * Cc) return;
    int c = idx % Cc;
    int s = (idx / Cc) % SLc;
    int b = idx / ((long)SLc * Cc);
    int n = s / Kc, k = s % Kc;
    int t0 = n + k * CCc;
    const float* p = vw2 + ((long)b * Tc + t0) * Cc + c;
    qq[idx] = 0.25f * (p[0] + p[Cc] + p[2 * Cc] + p[3 * Cc]) + b_v2[c];
}

// ---------------- per-chunk label mode ----------------
__global__ void mode_kernel(const int* __restrict__ labels, int* __restrict__ mode)
{
    int idx = blockIdx.x * blockDim.x + threadIdx.x;
    if (idx >= Bc * SLc) return;
    int b = idx / SLc, s = idx % SLc;
    int n = s / Kc, k = s % Kc;
    const int base = b * Tc + n + k * CCc;
    int labs[4];
#pragma unroll
    for (int j = 0; j < 4; j++) labs[j] = labels[base + j];
    int bestl = LQc, bestc = 0;
#pragma unroll
    for (int j = 0; j < 4; j++) {
        int cnt = 0;
#pragma unroll
        for (int j2 = 0; j2 < 4; j2++) cnt += (labs[j2] == labs[j]);
        if (cnt > bestc || (cnt == bestc && labs[j] < bestl)) { bestc = cnt; bestl = labs[j]; }
    }
    mode[idx] = bestl;
}

// ---------------- gather K-head rows by mode ----------------
__global__ void gather_kernel(const float* __restrict__ e2k, const int* __restrict__ mode,
                              float* __restrict__ khmat)
{
    long idx = (long)blockIdx.x * blockDim.x + threadIdx.x;
    if (idx >= (long)Bc * SLc * Cc) return;
    int c = idx % Cc;
    int s = (idx / Cc) % SLc;
    int b = idx / ((long)SLc * Cc);
    int m = mode[b * SLc + s];
    khmat[idx] = e2k[((long)b * LQc + m) * Cc + c];
}

// ---------------- row softmax ----------------
__global__ void softmax_kernel(float* __restrict__ scores)
{
    const long row = blockIdx.x;
    float* p = scores + row * (long)SLc;
    __shared__ float red[8];
    const int tid = threadIdx.x;         // 256
    const int lane = tid & 31, warp = tid >> 5;

    float m = -INFINITY;
    for (int i = tid; i < SLc; i += 256) m = fmaxf(m, p[i]);
#pragma unroll
    for (int o = 16; o; o >>= 1) m = fmaxf(m, __shfl_down_sync(0xffffffff, m, o));
    if (lane == 0) red[warp] = m;
    __syncthreads();
    if (tid == 0) {
        float mm = red[0];
#pragma unroll
        for (int w = 1; w < 8; w++) mm = fmaxf(mm, red[w]);
        red[0] = mm;
    }
    __syncthreads();
    m = red[0];
    __syncthreads();

    float s = 0.f;
    for (int i = tid; i < SLc; i += 256) { float e = expf(p[i] - m); p[i] = e; s += e; }
#pragma unroll
    for (int o = 16; o; o >>= 1) s += __shfl_down_sync(0xffffffff, s, o);
    if (lane == 0) red[warp] = s;
    __syncthreads();
    if (tid == 0) {
        float ss = 0.f;
#pragma unroll
        for (int w = 0; w < 8; w++) ss += red[w];
        red[0] = 1.f / ss;
    }
    __syncthreads();
    float inv = red[0];
    for (int i = tid; i < SLc; i += 256) p[i] *= inv;
}

// ---------------- pred head: (h @ w_p2^T + b_p2) transposed ----------------
__global__ void pred_kernel(const float* __restrict__ h, const float* __restrict__ w_p2,
                            const float* __restrict__ b_p2, float* __restrict__ out)
{
    const int bn = blockIdx.x;           // b*NW + n
    const float* hr = h + (long)bn * Cc;
    __shared__ float r0[8], r1[8];
    const int tid = threadIdx.x, lane = tid & 31, warp = tid >> 5;
    float s0 = 0.f, s1 = 0.f;
    for (int i = tid; i < Cc; i += 256) {
        float hv = hr[i];
        s0 += hv * w_p2[i];
        s1 += hv * w_p2[Cc + i];
    }
#pragma unroll
    for (int o = 16; o; o >>= 1) {
        s0 += __shfl_down_sync(0xffffffff, s0, o);
        s1 += __shfl_down_sync(0xffffffff, s1, o);
    }
    if (lane == 0) { r0[warp] = s0; r1[warp] = s1; }
    __syncthreads();
    if (tid == 0) {
        float t0 = 0.f, t1 = 0.f;
#pragma unroll
        for (int w = 0; w < 8; w++) { t0 += r0[w]; t1 += r1[w]; }
        int b = bn / NWc, n = bn % NWc;
        out[(long)b * 2 * NWc + n] = t0 + b_p2[0];
        out[(long)b * 2 * NWc + NWc + n] = t1 + b_p2[1];
    }
}

// ---------------- segment max pooling ----------------
__global__ void segmax_kernel(const float* __restrict__ outb, const int* __restrict__ vid_len,
                              float* __restrict__ mp)
{
    int idx = blockIdx.x * blockDim.x + threadIdx.x;
    if (idx >= Bc * Sc * Cc) return;
    int c = idx % Cc;
    int s = (idx / Cc) % Sc;
    int b = idx / (Sc * Cc);
    int Lb = vid_len[b] * Kc;
    int st = (s * Lb) / Sc;
    int en = ((s + 1) * Lb + Sc - 1) / Sc;
    float m = -INFINITY;
    const float* p = outb + ((long)b * SLc) * Cc + c;
    for (int t = st; t < en; t++) m = fmaxf(m, p[(long)t * Cc]);
    mp[idx] = m;
}

// ---------------- st/en heads ----------------
__global__ void sten_kernel(const float* __restrict__ mp,
                            const float* __restrict__ w_st, const float* __restrict__ b_st,
                            const float* __restrict__ w_en, const float* __restrict__ b_en,
                            float* __restrict__ out)
{
    const int id = blockIdx.x;           // 0..127
    const int b = id >> 4;
    const int r = id & 15;
    const int which = r >> 3;
    const int i = r & 7;
    const float* wgt = (which ? w_en : w_st) + (long)i * (Cc * Sc);
    __shared__ float red[8];
    const int tid = threadIdx.x, lane = tid & 31, warp = tid >> 5;
    float s = 0.f;
    for (int j = tid; j < Cc * Sc; j += 256) {
        int cc = j / Sc, ss = j % Sc;
        s += mp[((long)b * Sc + ss) * Cc + cc] * wgt[j];
    }
#pragma unroll
    for (int o = 16; o; o >>= 1) s += __shfl_down_sync(0xffffffff, s, o);
    if (lane == 0) red[warp] = s;
    __syncthreads();
    if (tid == 0) {
        float t = 0.f;
#pragma unroll
        for (int w = 0; w < 8; w++) t += red[w];
        float bias = (which ? b_en : b_st)[i];
        out[PRED_SZ + which * (Bc * Sc) + b * Sc + i] = t + bias;
    }
}

// ---------------- host side ----------------
static inline dim3 gemm_grid(int M, int N, int batch) {
    return dim3((N + 63) / 64, (M + 63) / 64, batch);
}

extern "C" void kernel_launch(void* const* d_in, const int* in_sizes, int n_in,
                              void* d_out, int out_size)
{
    const float* vis   = (const float*)d_in[0];
    const float* query = (const float*)d_in[1];
    const int*   vlen  = (const int*)  d_in[2];
    const float* w_v1  = (const float*)d_in[3];
    const float* b_v1  = (const float*)d_in[4];
    const float* w_v2  = (const float*)d_in[5];
    const float* b_v2  = (const float*)d_in[6];
    const float* w_s1  = (const float*)d_in[7];
    const float* b_s1  = (const float*)d_in[8];
    const float* w_s2  = (const float*)d_in[9];
    const float* b_s2  = (const float*)d_in[10];
    const float* w_in  = (const float*)d_in[11];
    const float* b_in  = (const float*)d_in[12];
    const float* w_out = (const float*)d_in[13];
    const float* b_out = (const float*)d_in[14];
    const float* w_p1  = (const float*)d_in[15];
    const float* b_p1  = (const float*)d_in[16];
    const float* w_p2  = (const float*)d_in[17];
    const float* b_p2  = (const float*)d_in[18];
    const float* w_st  = (const float*)d_in[19];
    const float* b_st  = (const float*)d_in[20];
    const float* w_en  = (const float*)d_in[21];
    const float* b_en  = (const float*)d_in[22];
    float* out = (float*)d_out;

    float *xpe, *qpe, *v, *vw2, *e1, *e2, *e2k, *qq, *qbuf, *vbuf, *khmat,
          *scores, *attn, *outb, *hbuf, *mp;
    int *labels, *mode;
    cudaGetSymbolAddress((void**)&xpe,   g_xpe);
    cudaGetSymbolAddress((void**)&qpe,   g_qpe);
    cudaGetSymbolAddress((void**)&v,     g_v);
    cudaGetSymbolAddress((void**)&vw2,   g_vw2);
    cudaGetSymbolAddress((void**)&e1,    g_e1);
    cudaGetSymbolAddress((void**)&e2,    g_e2);
    cudaGetSymbolAddress((void**)&e2k,   g_e2k);
    cudaGetSymbolAddress((void**)&labels,g_labels);
    cudaGetSymbolAddress((void**)&mode,  g_mode);
    cudaGetSymbolAddress((void**)&qq,    g_qq);
    cudaGetSymbolAddress((void**)&qbuf,  g_qbuf);
    cudaGetSymbolAddress((void**)&vbuf,  g_vbuf);
    cudaGetSymbolAddress((void**)&khmat, g_khmat);
    cudaGetSymbolAddress((void**)&scores,g_scores);
    cudaGetSymbolAddress((void**)&attn,  g_attn);
    cudaGetSymbolAddress((void**)&outb,  g_outb);
    cudaGetSymbolAddress((void**)&hbuf,  g_hbuf);
    cudaGetSymbolAddress((void**)&mp,    g_mp);

    // 1. positional encodings
    {
        int n = Bc * Tc * Cc;
        add_pe_kernel<<<(n + 255) / 256, 256>>>(vis, xpe, n, Tc, Cc);
        n = Bc * LQc * QDc;
        add_pe_kernel<<<(n + 255) / 256, 256>>>(query, qpe, n, LQc, QDc);
    }

    // 2. v = PE(vis) @ w_v1^T + b_v1   (2048 x 1024 x 1024)
    gemm_kernel<true, false><<<gemm_grid(Bc * Tc, Cc, 1), 256>>>(
        xpe, Cc, 0, 0, w_v1, Cc, 0, 0, v, Cc, 0, 0,
        Bc * Tc, Cc, Cc, 1, b_v1, 1.f);

    // 3. e1/e2 = PE(q) @ w_s{1,2}^T + b   (192 x 1024 x 768)
    gemm_kernel<true, false><<<gemm_grid(Bc * LQc, Cc, 1), 256>>>(
        qpe, QDc, 0, 0, w_s1, QDc, 0, 0, e1, Cc, 0, 0,
        Bc * LQc, Cc, QDc, 1, b_s1, 1.f);
    gemm_kernel<true, false><<<gemm_grid(Bc * LQc, Cc, 1), 256>>>(
        qpe, QDc, 0, 0, w_s2, QDc, 0, 0, e2, Cc, 0, 0,
        Bc * LQc, Cc, QDc, 1, b_s2, 1.f);

    // 4. labels = argmax_l  v . e1
    sim_argmax_kernel<<<Bc * Tc, 128>>>(v, e1, labels);

    // 5. vw2 = v @ w_v2^T (bias folded into pooling)
    gemm_kernel<true, false><<<gemm_grid(Bc * Tc, Cc, 1), 256>>>(
        v, Cc, 0, 0, w_v2, Cc, 0, 0, vw2, Cc, 0, 0,
        Bc * Tc, Cc, Cc, 1, nullptr, 1.f);

    // 6. qq = windowed mean of vw2 + b_v2  (B,SL,C)
    {
        long n = (long)Bc * SLc * Cc;
        pool_kernel<<<(int)((n + 255) / 256), 256>>>(vw2, b_v2, qq);
    }

    // 7. mode of labels per chunk
    mode_kernel<<<(Bc * SLc + 255) / 256, 256>>>(labels, mode);

    // 8. e2k = e2 @ wk^T + bk  (K-projection on the 24 query rows, pre-gather)
    gemm_kernel<true, false><<<gemm_grid(Bc * LQc, Cc, 1), 256>>>(
        e2, Cc, 0, 0, w_in + (long)Cc * Cc, Cc, 0, 0, e2k, Cc, 0, 0,
        Bc * LQc, Cc, Cc, 1, b_in + Cc, 1.f);

    // 9. gather khmat[b,s,:] = e2k[b, mode[b,s], :]
    {
        long n = (long)Bc * SLc * Cc;
        gather_kernel<<<(int)((n + 255) / 256), 256>>>(e2k, mode, khmat);
    }

    // 10. Q / V projections of qq  (7712 x 1024 x 1024 each)
    gemm_kernel<true, false><<<gemm_grid(Bc * SLc, Cc, 1), 256>>>(
        qq, Cc, 0, 0, w_in, Cc, 0, 0, qbuf, Cc, 0, 0,
        Bc * SLc, Cc, Cc, 1, b_in, 1.f);
    gemm_kernel<true, false><<<gemm_grid(Bc * SLc, Cc, 1), 256>>>(
        qq, Cc, 0, 0, w_in + 2L * Cc * Cc, Cc, 0, 0, vbuf, Cc, 0, 0,
        Bc * SLc, Cc, Cc, 1, b_in + 2 * Cc, 1.f);

    // 11. scores[b,h] = (Q_h K_h^T) / 16   batch = B*H, bdiv = H
    gemm_kernel<true, false><<<gemm_grid(SLc, SLc, Bc * Hc), 256>>>(
        qbuf, Cc, (long)SLc * Cc, HDc,
        khmat, Cc, (long)SLc * Cc, HDc,
        scores, SLc, (long)Hc * SLc * SLc, (long)SLc * SLc,
        SLc, SLc, HDc, Hc, nullptr, 1.f / 16.f);

    // 12. softmax rows
    softmax_kernel<<<Bc * Hc * SLc, 256>>>(scores);

    // 13. attn @ V   (NN, batch = B*H)
    gemm_kernel<false, false><<<gemm_grid(SLc, HDc, Bc * Hc), 256>>>(
        scores, SLc, (long)Hc * SLc * SLc, (long)SLc * SLc,
        vbuf, Cc, (long)SLc * Cc, HDc,
        attn, Cc, (long)SLc * Cc, HDc,
        SLc, HDc, SLc, Hc, nullptr, 1.f);

    // 14. out = attn @ w_out^T + b_out
    gemm_kernel<true, false><<<gemm_grid(Bc * SLc, Cc, 1), 256>>>(
        attn, Cc, 0, 0, w_out, Cc, 0, 0, outb, Cc, 0, 0,
        Bc * SLc, Cc, Cc, 1, b_out, 1.f);

    // 15. h = relu(out.reshape(B,NW,4096) @ w_p1^T + b_p1)  (1928 x 1024 x 4096)
    gemm_kernel<true, true><<<gemm_grid(Bc * NWc, Cc, 1), 256>>>(
        outb, Kc * Cc, 0, 0, w_p1, Kc * Cc, 0, 0, hbuf, Cc, 0, 0,
        Bc * NWc, Cc, Kc * Cc, 1, b_p1, 1.f);

    // 16. pred head (writes out[0 .. 3855])
    pred_kernel<<<Bc * NWc, 256>>>(hbuf, w_p2, b_p2, out);

    // 17. segment max
    segmax_kernel<<<(Bc * Sc * Cc + 255) / 256, 256>>>(outb, vlen, mp);

    // 18. st/en heads (writes out[3856 .. 3983])
    sten_kernel<<<128, 256>>>(mp, w_st, b_st, w_en, b_en, out);
}

// round 3
// speedup vs baseline: 3.8398x; 3.8398x over previous
#include <cuda_runtime.h>
#include <cstdint>
#include <math.h>

// ---------------- problem constants ----------------
constexpr int Bc  = 8;
constexpr int Tc  = 256;
constexpr int Cc  = 1024;
constexpr int QDc = 768;
constexpr int LQc = 24;
constexpr int Kc  = 4;
constexpr int CCc = 4;       // W/K
constexpr int NWc = 241;     // T - W + 1
constexpr int Sc  = 8;
constexpr int Hc  = 4;
constexpr int HDc = 256;     // C/H
constexpr int SLc = 964;     // NW*K
constexpr int LHc = LQc * Hc; // 96

constexpr int PRED_SZ = Bc * 2 * NWc;  // 3856

// ---------------- scratch (device globals; no allocation allowed) ----------------
__device__ float g_xpe   [Bc * Tc * Cc];
__device__ float g_qpe   [Bc * LQc * QDc];
__device__ float g_v     [Bc * Tc * Cc];
__device__ float g_vw2   [Bc * Tc * Cc];
__device__ float g_e1    [Bc * LQc * Cc];
__device__ float g_e2    [Bc * LQc * Cc];
__device__ float g_e2k   [Bc * LQc * Cc];
__device__ int   g_labels[Bc * Tc];
__device__ int   g_mode  [Bc * SLc];
__device__ float g_cnt   [Bc * LQc];
__device__ float g_qq    [Bc * SLc * Cc];
__device__ float g_P     [Bc * LHc * Cc];
__device__ float g_bterm [Bc * LHc];
__device__ float g_su    [Bc * SLc * LHc];
__device__ float g_wcoef [Bc * SLc * LHc];
__device__ float g_qsum  [Bc * LQc * Cc];
__device__ float g_VS    [Bc * LQc * Cc];
__device__ float g_VSo   [Bc * LHc * Cc];
__device__ float g_outb  [Bc * SLc * Cc];
__device__ float g_hbuf  [Bc * NWc * Cc];
__device__ float g_mp    [Bc * Sc * Cc];

// ---------------- generic tiled GEMM (128x64 tile, 8x4 microtile) ----------------
// C[m,n] = alpha * sum_k A[m,k] * B(k,n)  (+ bias[n]) (+relu)
// TRANSB=true : B row-major (N,K)  -> B[n*ldb + k]   ("x @ W^T")
// TRANSB=false: B row-major (K,N)  -> B[k*ldb + n]
// batching: z = blockIdx.z ; z1 = z/bdiv ; z2 = z%bdiv; offsets = z1*s?1 + z2*s?2
// REQUIRES: K % 16 == 0, N % 4 == 0, lda/ldb/ldc % 4 == 0
template<bool TRANSB, bool RELU>
__global__ void gemm_kernel(const float* __restrict__ A, int lda, long sA1, long sA2,
                            const float* __restrict__ B, int ldb, long sB1, long sB2,
                            float* __restrict__ Cm, int ldc, long sC1, long sC2,
                            int M, int N, int K, int bdiv,
                            const float* __restrict__ bias, float alpha)
{
    const int z = blockIdx.z, z1 = z / bdiv, z2 = z % bdiv;
    A  += z1 * sA1 + z2 * sA2;
    B  += z1 * sB1 + z2 * sB2;
    Cm += z1 * sC1 + z2 * sC2;

    __shared__ float As[16][132];   // padded: conflict-light STS, 16B-aligned rows
    __shared__ float Bs[16][68];

    const int tid = threadIdx.x;        // 256 threads
    const int tx = tid & 15, ty = tid >> 4;
    const int rowBase = blockIdx.y * 128;
    const int colBase = blockIdx.x * 64;

    float acc[8][4] = {};

    for (int k0 = 0; k0 < K; k0 += 16) {
        // A tile: 128 x 16, 8 scalar loads per thread, coalesced along k
#pragma unroll
        for (int i = 0; i < 8; i++) {
            int l = tid + i * 256;
            int m = l >> 4, kk = l & 15;
            int gm = rowBase + m;
            As[kk][m] = (gm < M) ? A[(long)gm * lda + k0 + kk] : 0.f;
        }
        // B tile: 64 x 16, 4 per thread
#pragma unroll
        for (int i = 0; i < 4; i++) {
            int l = tid + i * 256;
            if (TRANSB) {
                int n = l >> 4, kk = l & 15;
                int gn = colBase + n;
                Bs[kk][n] = (gn < N) ? B[(long)gn * ldb + k0 + kk] : 0.f;
            } else {
                int kk = l >> 6, n = l & 63;
                int gn = colBase + n;
                Bs[kk][n] = (gn < N) ? B[(long)(k0 + kk) * ldb + gn] : 0.f;
            }
        }
        __syncthreads();
#pragma unroll
        for (int kk = 0; kk < 16; kk++) {
            float4 a0 = *(const float4*)&As[kk][ty * 8];
            float4 a1 = *(const float4*)&As[kk][ty * 8 + 4];
            float4 b0 = *(const float4*)&Bs[kk][tx * 4];
            float ra[8] = {a0.x, a0.y, a0.z, a0.w, a1.x, a1.y, a1.z, a1.w};
            float rb[4] = {b0.x, b0.y, b0.z, b0.w};
#pragma unroll
            for (int i = 0; i < 8; i++)
#pragma unroll
                for (int j = 0; j < 4; j++)
                    acc[i][j] += ra[i] * rb[j];
        }
        __syncthreads();
    }

#pragma unroll
    for (int i = 0; i < 8; i++) {
        int gm = rowBase + ty * 8 + i;
        if (gm >= M) continue;
        int gn0 = colBase + tx * 4;
#pragma unroll
        for (int j = 0; j < 4; j++) {
            int gn = gn0 + j;
            if (gn >= N) continue;
            float val = acc[i][j] * alpha + (bias ? bias[gn] : 0.f);
            if (RELU) val = fmaxf(val, 0.f);
            Cm[(long)gm * ldc + gn] = val;
        }
    }
}

// ---------------- positional encoding add ----------------
__global__ void add_pe_kernel(const float* __restrict__ src, float* __restrict__ dst,
                              int n, int L, int D)
{
    int idx = blockIdx.x * blockDim.x + threadIdx.x;
    if (idx >= n) return;
    int c = idx % D;
    int pos = (idx / D) % L;
    int i2 = (c >> 1) * 2;
    float freq = expf((float)i2 * (-logf(10000.f) / (float)D));
    float ang = (float)pos * freq;
    float pe = (c & 1) ? cosf(ang) : sinf(ang);
    dst[idx] = src[idx] + pe;
}

// ---------------- sim + argmax(labels) fused ----------------
__global__ void sim_argmax_kernel(const float* __restrict__ v, const float* __restrict__ e1,
                                  int* __restrict__ labels)
{
    const int bt = blockIdx.x;          // b*T + t
    const int b = bt / Tc;
    __shared__ float sv[Cc];
    __shared__ float red[4];
    const int tid = threadIdx.x;        // 128 threads
    const int lane = tid & 31, warp = tid >> 5;

    const float* vrow = v + (long)bt * Cc;
    for (int i = tid; i < Cc; i += 128) sv[i] = vrow[i];
    __syncthreads();

    __shared__ float best;
    __shared__ int bestl;
    if (tid == 0) { best = -INFINITY; bestl = 0; }
    __syncthreads();

    for (int l = 0; l < LQc; l++) {
        const float* er = e1 + ((long)b * LQc + l) * Cc;
        float s = 0.f;
        for (int i = tid; i < Cc; i += 128) s += sv[i] * er[i];
#pragma unroll
        for (int o = 16; o; o >>= 1) s += __shfl_down_sync(0xffffffff, s, o);
        if (lane == 0) red[warp] = s;
        __syncthreads();
        if (tid == 0) {
            float tot = red[0] + red[1] + red[2] + red[3];
            if (tot > best) { best = tot; bestl = l; }
        }
        __syncthreads();
    }
    if (tid == 0) labels[bt] = bestl;
}

// ---------------- window mean pooling (+ b_v2) ----------------
__global__ void pool_kernel(const float* __restrict__ vw2, const float* __restrict__ b_v2,
                            float* __restrict__ qq)
{
    long idx = (long)blockIdx.x * blockDim.x + threadIdx.x;
    if (idx >= (long)Bc * SLc * Cc) return;
    int c = idx % Cc;
    int s = (idx / Cc) % SLc;
    int b = idx / ((long)SLc * Cc);
    int n = s / Kc, k = s % Kc;
    int t0 = n + k * CCc;
    const float* p = vw2 + ((long)b * Tc + t0) * Cc + c;
    qq[idx] = 0.25f * (p[0] + p[Cc] + p[2 * Cc] + p[3 * Cc]) + b_v2[c];
}

// ---------------- per-chunk label mode ----------------
__global__ void mode_kernel(const int* __restrict__ labels, int* __restrict__ mode)
{
    int idx = blockIdx.x * blockDim.x + threadIdx.x;
    if (idx >= Bc * SLc) return;
    int b = idx / SLc, s = idx % SLc;
    int n = s / Kc, k = s % Kc;
    const int base = b * Tc + n + k * CCc;
    int labs[4];
#pragma unroll
    for (int j = 0; j < 4; j++) labs[j] = labels[base + j];
    int bestl = LQc, bestc = 0;
#pragma unroll
    for (int j = 0; j < 4; j++) {
        int cnt = 0;
#pragma unroll
        for (int j2 = 0; j2 < 4; j2++) cnt += (labs[j2] == labs[j]);
        if (cnt > bestc || (cnt == bestc && labs[j] < bestl)) { bestc = cnt; bestl = labs[j]; }
    }
    mode[idx] = bestl;
}

// ---------------- label counts per (b, l) ----------------
__global__ void count_kernel(const int* __restrict__ mode, float* __restrict__ cnt)
{
    int idx = blockIdx.x * blockDim.x + threadIdx.x;
    if (idx >= Bc * LQc) return;
    int b = idx / LQc, l = idx % LQc;
    int c = 0;
    const int* m = mode + b * SLc;
    for (int s = 0; s < SLc; s++) c += (m[s] == l);
    cnt[idx] = (float)c;
}

// ---------------- bterm[b, l*H+h] = bq_h . e2k_h[b,l] ----------------
__global__ void bterm_kernel(const float* __restrict__ e2k, const float* __restrict__ b_in,
                             float* __restrict__ bterm)
{
    int idx = blockIdx.x * blockDim.x + threadIdx.x;
    if (idx >= Bc * LHc) return;
    int b = idx / LHc, j = idx % LHc;
    int l = j / Hc, h = j % Hc;
    const float* e = e2k + ((long)b * LQc + l) * Cc + h * HDc;
    const float* bq = b_in + h * HDc;   // q-proj bias, head h slice
    float s = 0.f;
    for (int d = 0; d < HDc; d++) s += bq[d] * e[d];
    bterm[idx] = s;
}

// ---------------- softmax weights over 24 labels per (b,q,h) ----------------
__global__ void attnw_kernel(const float* __restrict__ su, const float* __restrict__ bterm,
                             const float* __restrict__ cnt, float* __restrict__ wcoef)
{
    const int bq = blockIdx.x;          // b*SL + q
    const int b = bq / SLc;
    const int tid = threadIdx.x;        // 128: warp = head
    const int h = tid >> 5, l = tid & 31;
    const bool act = (l < LQc);
    const int j = l * Hc + h;
    const long base = (long)bq * LHc;

    float c_l = act ? cnt[b * LQc + l] : 0.f;
    float val = act ? (su[base + j] + bterm[b * LHc + j] * (1.f / 16.f)) : -INFINITY;
    float mval = (act && c_l > 0.f) ? val : -INFINITY;
#pragma unroll
    for (int o = 16; o; o >>= 1) mval = fmaxf(mval, __shfl_xor_sync(0xffffffff, mval, o));
    float e = act ? expf(val - mval) : 0.f;
    float zz = c_l * e;
#pragma unroll
    for (int o = 16; o; o >>= 1) zz += __shfl_xor_sync(0xffffffff, zz, o);
    if (act) wcoef[base + j] = (c_l > 0.f) ? (e / zz) : 0.f;
}

// ---------------- qsum[b,l,c] = sum over s with mode==l of qq[b,s,c] ----------------
__global__ void qsum_kernel(const float* __restrict__ qq, const int* __restrict__ mode,
                            float* __restrict__ qsum)
{
    // grid: Bc * (Cc/256) blocks of 256 threads
    const int b = blockIdx.x / (Cc / 256);
    const int chunk = blockIdx.x % (Cc / 256);
    __shared__ float acc[LQc * 256];
    __shared__ int sm[SLc];
    const int tid = threadIdx.x;
    for (int l = 0; l < LQc; l++) acc[l * 256 + tid] = 0.f;
    for (int s = tid; s < SLc; s += 256) sm[s] = mode[b * SLc + s];
    __syncthreads();
    const float* base = qq + (long)b * SLc * Cc + chunk * 256 + tid;
    float racc = 0.f;
    int cur = sm[0];
    for (int s = 0; s < SLc; s++) {
        int m = sm[s];
        float v = base[(long)s * Cc];
        if (m != cur) { acc[cur * 256 + tid] += racc; racc = 0.f; cur = m; }
        racc += v;
    }
    acc[cur * 256 + tid] += racc;
    __syncthreads();
    for (int l = 0; l < LQc; l++)
        qsum[((long)b * LQc + l) * Cc + chunk * 256 + tid] = acc[l * 256 + tid];
}

// ---------------- VS += cnt * b_v  (v-proj bias for summed groups) ----------------
__global__ void vsfix_kernel(float* __restrict__ VS, const float* __restrict__ cnt,
                             const float* __restrict__ bv)
{
    int idx = blockIdx.x * blockDim.x + threadIdx.x;
    if (idx >= Bc * LQc * Cc) return;
    int c = idx % Cc;
    int bl = idx / Cc;
    VS[idx] += cnt[bl] * bv[c];
}

// ---------------- pred head: (h @ w_p2^T + b_p2) transposed ----------------
__global__ void pred_kernel(const float* __restrict__ h, const float* __restrict__ w_p2,
                            const float* __restrict__ b_p2, float* __restrict__ out)
{
    const int bn = blockIdx.x;           // b*NW + n
    const float* hr = h + (long)bn * Cc;
    __shared__ float r0[8], r1[8];
    const int tid = threadIdx.x, lane = tid & 31, warp = tid >> 5;
    float s0 = 0.f, s1 = 0.f;
    for (int i = tid; i < Cc; i += 256) {
        float hv = hr[i];
        s0 += hv * w_p2[i];
        s1 += hv * w_p2[Cc + i];
    }
#pragma unroll
    for (int o = 16; o; o >>= 1) {
        s0 += __shfl_down_sync(0xffffffff, s0, o);
        s1 += __shfl_down_sync(0xffffffff, s1, o);
    }
    if (lane == 0) { r0[warp] = s0; r1[warp] = s1; }
    __syncthreads();
    if (tid == 0) {
        float t0 = 0.f, t1 = 0.f;
#pragma unroll
        for (int w = 0; w < 8; w++) { t0 += r0[w]; t1 += r1[w]; }
        int b = bn / NWc, n = bn % NWc;
        out[(long)b * 2 * NWc + n] = t0 + b_p2[0];
        out[(long)b * 2 * NWc + NWc + n] = t1 + b_p2[1];
    }
}

// ---------------- segment max pooling ----------------
__global__ void segmax_kernel(const float* __restrict__ outb, const int* __restrict__ vid_len,
                              float* __restrict__ mp)
{
    int idx = blockIdx.x * blockDim.x + threadIdx.x;
    if (idx >= Bc * Sc * Cc) return;
    int c = idx % Cc;
    int s = (idx / Cc) % Sc;
    int b = idx / (Sc * Cc);
    int Lb = vid_len[b] * Kc;
    int st = (s * Lb) / Sc;
    int en = ((s + 1) * Lb + Sc - 1) / Sc;
    float m = -INFINITY;
    const float* p = outb + ((long)b * SLc) * Cc + c;
    for (int t = st; t < en; t++) m = fmaxf(m, p[(long)t * Cc]);
    mp[idx] = m;
}

// ---------------- st/en heads ----------------
__global__ void sten_kernel(const float* __restrict__ mp,
                            const float* __restrict__ w_st, const float* __restrict__ b_st,
                            const float* __restrict__ w_en, const float* __restrict__ b_en,
                            float* __restrict__ out)
{
    const int id = blockIdx.x;           // 0..127
    const int b = id >> 4;
    const int r = id & 15;
    const int which = r >> 3;
    const int i = r & 7;
    const float* wgt = (which ? w_en : w_st) + (long)i * (Cc * Sc);
    __shared__ float red[8];
    const int tid = threadIdx.x, lane = tid & 31, warp = tid >> 5;
    float s = 0.f;
    for (int j = tid; j < Cc * Sc; j += 256) {
        int cc = j / Sc, ss = j % Sc;
        s += mp[((long)b * Sc + ss) * Cc + cc] * wgt[j];
    }
#pragma unroll
    for (int o = 16; o; o >>= 1) s += __shfl_down_sync(0xffffffff, s, o);
    if (lane == 0) red[warp] = s;
    __syncthreads();
    if (tid == 0) {
        float t = 0.f;
#pragma unroll
        for (int w = 0; w < 8; w++) t += red[w];
        float bias = (which ? b_en : b_st)[i];
        out[PRED_SZ + which * (Bc * Sc) + b * Sc + i] = t + bias;
    }
}

// ---------------- host side ----------------
static inline dim3 gemm_grid(int M, int N, int batch) {
    return dim3((N + 63) / 64, (M + 127) / 128, batch);
}

extern "C" void kernel_launch(void* const* d_in, const int* in_sizes, int n_in,
                              void* d_out, int out_size)
{
    const float* vis   = (const float*)d_in[0];
    const float* query = (const float*)d_in[1];
    const int*   vlen  = (const int*)  d_in[2];
    const float* w_v1  = (const float*)d_in[3];
    const float* b_v1  = (const float*)d_in[4];
    const float* w_v2  = (const float*)d_in[5];
    const float* b_v2  = (const float*)d_in[6];
    const float* w_s1  = (const float*)d_in[7];
    const float* b_s1  = (const float*)d_in[8];
    const float* w_s2  = (const float*)d_in[9];
    const float* b_s2  = (const float*)d_in[10];
    const float* w_in  = (const float*)d_in[11];
    const float* b_in  = (const float*)d_in[12];
    const float* w_out = (const float*)d_in[13];
    const float* b_out = (const float*)d_in[14];
    const float* w_p1  = (const float*)d_in[15];
    const float* b_p1  = (const float*)d_in[16];
    const float* w_p2  = (const float*)d_in[17];
    const float* b_p2  = (const float*)d_in[18];
    const float* w_st  = (const float*)d_in[19];
    const float* b_st  = (const float*)d_in[20];
    const float* w_en  = (const float*)d_in[21];
    const float* b_en  = (const float*)d_in[22];
    float* out = (float*)d_out;

    float *xpe, *qpe, *v, *vw2, *e1, *e2, *e2k, *cnt, *qq, *P, *bterm, *su,
          *wcoef, *qsum, *VS, *VSo, *outb, *hbuf, *mp;
    int *labels, *mode;
    cudaGetSymbolAddress((void**)&xpe,   g_xpe);
    cudaGetSymbolAddress((void**)&qpe,   g_qpe);
    cudaGetSymbolAddress((void**)&v,     g_v);
    cudaGetSymbolAddress((void**)&vw2,   g_vw2);
    cudaGetSymbolAddress((void**)&e1,    g_e1);
    cudaGetSymbolAddress((void**)&e2,    g_e2);
    cudaGetSymbolAddress((void**)&e2k,   g_e2k);
    cudaGetSymbolAddress((void**)&labels,g_labels);
    cudaGetSymbolAddress((void**)&mode,  g_mode);
    cudaGetSymbolAddress((void**)&cnt,   g_cnt);
    cudaGetSymbolAddress((void**)&qq,    g_qq);
    cudaGetSymbolAddress((void**)&P,     g_P);
    cudaGetSymbolAddress((void**)&bterm, g_bterm);
    cudaGetSymbolAddress((void**)&su,    g_su);
    cudaGetSymbolAddress((void**)&wcoef, g_wcoef);
    cudaGetSymbolAddress((void**)&qsum,  g_qsum);
    cudaGetSymbolAddress((void**)&VS,    g_VS);
    cudaGetSymbolAddress((void**)&VSo,   g_VSo);
    cudaGetSymbolAddress((void**)&outb,  g_outb);
    cudaGetSymbolAddress((void**)&hbuf,  g_hbuf);
    cudaGetSymbolAddress((void**)&mp,    g_mp);

    // 1. positional encodings
    {
        int n = Bc * Tc * Cc;
        add_pe_kernel<<<(n + 255) / 256, 256>>>(vis, xpe, n, Tc, Cc);
        n = Bc * LQc * QDc;
        add_pe_kernel<<<(n + 255) / 256, 256>>>(query, qpe, n, LQc, QDc);
    }

    // 2. v = PE(vis) @ w_v1^T + b_v1
    gemm_kernel<true, false><<<gemm_grid(Bc * Tc, Cc, 1), 256>>>(
        xpe, Cc, 0, 0, w_v1, Cc, 0, 0, v, Cc, 0, 0,
        Bc * Tc, Cc, Cc, 1, b_v1, 1.f);

    // 3. e1/e2 = PE(q) @ w_s{1,2}^T + b
    gemm_kernel<true, false><<<gemm_grid(Bc * LQc, Cc, 1), 256>>>(
        qpe, QDc, 0, 0, w_s1, QDc, 0, 0, e1, Cc, 0, 0,
        Bc * LQc, Cc, QDc, 1, b_s1, 1.f);
    gemm_kernel<true, false><<<gemm_grid(Bc * LQc, Cc, 1), 256>>>(
        qpe, QDc, 0, 0, w_s2, QDc, 0, 0, e2, Cc, 0, 0,
        Bc * LQc, Cc, QDc, 1, b_s2, 1.f);

    // 4. labels = argmax_l v . e1
    sim_argmax_kernel<<<Bc * Tc, 128>>>(v, e1, labels);

    // 5. vw2 = v @ w_v2^T (bias folded into pooling)
    gemm_kernel<true, false><<<gemm_grid(Bc * Tc, Cc, 1), 256>>>(
        v, Cc, 0, 0, w_v2, Cc, 0, 0, vw2, Cc, 0, 0,
        Bc * Tc, Cc, Cc, 1, nullptr, 1.f);

    // 6. qq = windowed mean + b_v2
    {
        long n = (long)Bc * SLc * Cc;
        pool_kernel<<<(int)((n + 255) / 256), 256>>>(vw2, b_v2, qq);
    }

    // 7. mode + counts
    mode_kernel<<<(Bc * SLc + 255) / 256, 256>>>(labels, mode);
    count_kernel<<<1, Bc * LQc>>>(mode, cnt);

    // 8. e2k = e2 @ wk^T + bk
    gemm_kernel<true, false><<<gemm_grid(Bc * LQc, Cc, 1), 256>>>(
        e2, Cc, 0, 0, w_in + (long)Cc * Cc, Cc, 0, 0, e2k, Cc, 0, 0,
        Bc * LQc, Cc, Cc, 1, b_in + Cc, 1.f);

    // 9. P[b, l*H+h, c] = sum_d wq[h*HD+d, c] * e2k[b,l,h*HD+d]   (batch B*H, NN)
    gemm_kernel<false, false><<<gemm_grid(LQc, Cc, Bc * Hc), 256>>>(
        e2k, Cc, (long)LQc * Cc, HDc,
        w_in, Cc, 0, (long)HDc * Cc,
        P, Hc * Cc, (long)LHc * Cc, Cc,
        LQc, Cc, HDc, Hc, nullptr, 1.f);

    // 10. bterm[b,j] = bq_h . e2k_h[b,l]
    bterm_kernel<<<(Bc * LHc + 255) / 256, 256>>>(e2k, b_in, bterm);

    // 11. su[b,q,j] = (qq . P) / 16   (batch B, TRANSB)
    gemm_kernel<true, false><<<gemm_grid(SLc, LHc, Bc), 256>>>(
        qq, Cc, (long)SLc * Cc, 0,
        P, Cc, (long)LHc * Cc, 0,
        su, LHc, (long)SLc * LHc, 0,
        SLc, LHc, Cc, 1, nullptr, 1.f / 16.f);

    // 12. softmax weights over 24 labels (counted)
    attnw_kernel<<<Bc * SLc, 128>>>(su, bterm, cnt, wcoef);

    // 13. qsum (group-sum of qq rows by mode)
    qsum_kernel<<<Bc * (Cc / 256), 256>>>(qq, mode, qsum);

    // 14. VS = qsum @ wv^T ; then += cnt * bv
    gemm_kernel<true, false><<<gemm_grid(Bc * LQc, Cc, 1), 256>>>(
        qsum, Cc, 0, 0, w_in + 2L * Cc * Cc, Cc, 0, 0, VS, Cc, 0, 0,
        Bc * LQc, Cc, Cc, 1, nullptr, 1.f);
    vsfix_kernel<<<(Bc * LQc * Cc + 255) / 256, 256>>>(VS, cnt, b_in + 2 * Cc);

    // 15. VSo[b, l*H+h, c'] = VS_h[b,l] @ w_out_h^T   (batch B*H, TRANSB)
    gemm_kernel<true, false><<<gemm_grid(LQc, Cc, Bc * Hc), 256>>>(
        VS, Cc, (long)LQc * Cc, HDc,
        w_out, Cc, 0, HDc,
        VSo, Hc * Cc, (long)LHc * Cc, Cc,
        LQc, Cc, HDc, Hc, nullptr, 1.f);

    // 16. outb = wcoef @ VSo + b_out   (batch B, NN, K=96)
    gemm_kernel<false, false><<<gemm_grid(SLc, Cc, Bc), 256>>>(
        wcoef, LHc, (long)SLc * LHc, 0,
        VSo, Cc, (long)LHc * Cc, 0,
        outb, Cc, (long)SLc * Cc, 0,
        SLc, Cc, LHc, 1, b_out, 1.f);

    // 17. h = relu(outb.reshape(B,NW,4C) @ w_p1^T + b_p1)
    gemm_kernel<true, true><<<gemm_grid(Bc * NWc, Cc, 1), 256>>>(
        outb, Kc * Cc, 0, 0, w_p1, Kc * Cc, 0, 0, hbuf, Cc, 0, 0,
        Bc * NWc, Cc, Kc * Cc, 1, b_p1, 1.f);

    // 18. pred head
    pred_kernel<<<Bc * NWc, 256>>>(hbuf, w_p2, b_p2, out);

    // 19. segment max + st/en heads
    segmax_kernel<<<(Bc * Sc * Cc + 255) / 256, 256>>>(outb, vlen, mp);
    sten_kernel<<<128, 256>>>(mp, w_st, b_st, w_en, b_en, out);
}